// round 3
// baseline (speedup 1.0000x reference)
#include <cuda_runtime.h>
#include <cstdint>

#define NMAX 200000
#define H_DIM 184
#define L1_DIM 188

// Scratch (no allocations allowed)
__device__ float4       g_agg[NMAX];      // per-node weighted feature sum
__device__ float        g_deg[NMAX];      // per-node degree
__device__ float4       g_x4[NMAX];       // packed node_feat[:, :4]
__device__ unsigned int g_x1[H_DIM];      // column max of h (uint bits; h>=0)
__device__ float        g_x2[H_DIM];      // h[center]
__device__ float        g_md[16];         // md MLP output (depends on nf only)
__device__ unsigned int g_ctr;            // block-completion counter

// ---------------------------------------------------------------------------
// Kernel 0: zero scratch, pack node_feat[:, :4], compute md MLP (warp 0 blk 0)
// ---------------------------------------------------------------------------
__global__ void prep_kernel(const float* __restrict__ nf, int n_nodes,
                            const int*   __restrict__ center,
                            const float* __restrict__ W2,  const float* __restrict__ b2,
                            const float* __restrict__ W21, const float* __restrict__ b21) {
    int stride = gridDim.x * blockDim.x;
    int tid = blockIdx.x * blockDim.x + threadIdx.x;

    if (tid == 0) g_ctr = 0u;

    // md = relu(relu(nf[c,4:6]@W2+b2)@W21+b21)   (block 0, warp 0)
    if (blockIdx.x == 0 && threadIdx.x < 32) {
        int t = threadIdx.x;
        int c = *center;
        float m0 = nf[(size_t)c * 6 + 4];
        float m1 = nf[(size_t)c * 6 + 5];
        float md1 = 0.0f;
        if (t < 16)
            md1 = fmaxf(fmaf(m0, W2[t], fmaf(m1, W2[16 + t], b2[t])), 0.0f);
        // broadcast md1 lanes 0..15 via shuffle
        float s = (t < 16) ? b21[t] : 0.0f;
        #pragma unroll
        for (int k = 0; k < 16; k++) {
            float v = __shfl_sync(0xffffffff, md1, k);
            if (t < 16) s = fmaf(v, W21[k * 16 + t], s);
        }
        if (t < 16) g_md[t] = fmaxf(s, 0.0f);
    }

    // zero agg + deg + x1
    float* aggf = reinterpret_cast<float*>(g_agg);
    int total = n_nodes * 5 + H_DIM;
    for (int i = tid; i < total; i += stride) {
        if (i < n_nodes * 4)       aggf[i] = 0.0f;
        else if (i < n_nodes * 5)  g_deg[i - n_nodes * 4] = 0.0f;
        else                       g_x1[i - n_nodes * 5] = 0u;
    }
    // pack first 4 features (row stride 6 -> two aligned float2 loads)
    for (int i = tid; i < n_nodes; i += stride) {
        const float2* p = reinterpret_cast<const float2*>(nf + (size_t)i * 6);
        float2 a = __ldg(p);
        float2 b = __ldg(p + 1);
        g_x4[i] = make_float4(a.x, a.y, b.x, b.y);
    }
}

// ---------------------------------------------------------------------------
// Kernel 1: edge scatter.  One LDG.128 gather + one red.v4 + one red per edge.
// ---------------------------------------------------------------------------
__device__ __forceinline__ void do_edge(int s, int d, float w) {
    float4 x = __ldg(&g_x4[s]);                  // single 16B gather
    float* ap = reinterpret_cast<float*>(&g_agg[d]);
    asm volatile("red.global.add.v4.f32 [%0], {%1, %2, %3, %4};"
                 :: "l"(ap), "f"(x.x * w), "f"(x.y * w),
                    "f"(x.z * w), "f"(x.w * w)
                 : "memory");
    asm volatile("red.global.add.f32 [%0], %1;"
                 :: "l"(&g_deg[d]), "f"(1.0f) : "memory");
}

__global__ void __launch_bounds__(256) edge_kernel(const int*   __restrict__ ei,
                                                   const float* __restrict__ ew, int E) {
    int i    = blockIdx.x * blockDim.x + threadIdx.x;
    int nvec = E >> 2;
    if (i < nvec) {
        int4   s = __ldcs(reinterpret_cast<const int4*>(ei) + i);
        int4   d = __ldcs(reinterpret_cast<const int4*>(ei + E) + i);
        float4 w = __ldcs(reinterpret_cast<const float4*>(ew) + i);
        do_edge(s.x, d.x, w.x);
        do_edge(s.y, d.y, w.y);
        do_edge(s.z, d.z, w.z);
        do_edge(s.w, d.w, w.w);
    }
    if (i == 0) {                                // tail (E % 4)
        for (int e = nvec * 4; e < E; e++)
            do_edge(ei[e], ei[E + e], ew[e]);
    }
}

// ---------------------------------------------------------------------------
// Kernel 2: per-node h + column max; last block finishes with the head MLP.
// ---------------------------------------------------------------------------
__global__ void __launch_bounds__(192) node_kernel(
        const float* __restrict__ Wrel,
        const float* __restrict__ brel,
        const float* __restrict__ Wroot,
        int N, const int* __restrict__ center,
        const float* __restrict__ W1, const float* __restrict__ b1,
        const float* __restrict__ W4, const float* __restrict__ b4,
        float* __restrict__ out) {
    int j = threadIdx.x;
    int c = *center;

    if (j < H_DIM) {
        float wr0 = Wrel[j],             wr1 = Wrel[H_DIM + j];
        float wr2 = Wrel[2 * H_DIM + j], wr3 = Wrel[3 * H_DIM + j];
        float wo0 = Wroot[j],            wo1 = Wroot[H_DIM + j];
        float wo2 = Wroot[2 * H_DIM + j], wo3 = Wroot[3 * H_DIM + j];
        float bj  = brel[j];

        float m = 0.0f;                          // h >= 0 after ReLU
        for (int node = blockIdx.x; node < N; node += gridDim.x) {
            float4 agg = g_agg[node];            // broadcast within block
            float  deg = g_deg[node];
            float4 x   = g_x4[node];
            float  inv = 1.0f / fmaxf(deg, 1.0f);
            float h = bj;
            h = fmaf(agg.x * inv, wr0, h);
            h = fmaf(agg.y * inv, wr1, h);
            h = fmaf(agg.z * inv, wr2, h);
            h = fmaf(agg.w * inv, wr3, h);
            h = fmaf(x.x, wo0, h);
            h = fmaf(x.y, wo1, h);
            h = fmaf(x.z, wo2, h);
            h = fmaf(x.w, wo3, h);
            h = fmaxf(h, 0.0f);
            m = fmaxf(m, h);
            if (node == c) g_x2[j] = h;
        }
        atomicMax(&g_x1[j], __float_as_uint(m));
    }

    // ---- last-block head ----
    __shared__ bool is_last;
    __threadfence();
    __syncthreads();
    if (threadIdx.x == 0)
        is_last = (atomicAdd(&g_ctr, 1u) == (unsigned)gridDim.x - 1u);
    __syncthreads();
    if (!is_last) return;

    __shared__ float gvec[H_DIM + 16];           // [x2-x1 (184), md (16)]
    __shared__ float g1[L1_DIM];
    int t = threadIdx.x;

    for (int k = t; k < H_DIM + 16; k += blockDim.x) {
        if (k < H_DIM)
            gvec[k] = __ldcg(&g_x2[k]) - __uint_as_float(__ldcg(&g_x1[k]));
        else
            gvec[k] = g_md[k - H_DIM];
    }
    __syncthreads();

    if (t < L1_DIM) {
        float s = b1[t];
        #pragma unroll 8
        for (int k = 0; k < H_DIM + 16; k++)
            s = fmaf(gvec[k], W1[k * L1_DIM + t], s);
        g1[t] = fmaxf(s, 0.0f);
    }
    __syncthreads();

    // out = g1 @ W4 + b4 : one warp per output, lanes split k
    if (t < 160) {
        int o    = t >> 5;
        int lane = t & 31;
        float s = 0.0f;
        for (int k = lane; k < L1_DIM; k += 32)
            s = fmaf(g1[k], W4[k * 5 + o], s);
        #pragma unroll
        for (int off = 16; off > 0; off >>= 1)
            s += __shfl_down_sync(0xffffffff, s, off);
        if (lane == 0) out[o] = s + b4[o];
    }
}

// ---------------------------------------------------------------------------
extern "C" void kernel_launch(void* const* d_in, const int* in_sizes, int n_in,
                              void* d_out, int out_size) {
    const float* nf     = (const float*)d_in[0];
    const int*   ei     = (const int*)  d_in[1];
    const float* ew     = (const float*)d_in[2];
    const int*   center = (const int*)  d_in[3];
    const float* Wrel   = (const float*)d_in[4];
    const float* brel   = (const float*)d_in[5];
    const float* Wroot  = (const float*)d_in[6];
    const float* W2     = (const float*)d_in[7];
    const float* b2     = (const float*)d_in[8];
    const float* W21    = (const float*)d_in[9];
    const float* b21    = (const float*)d_in[10];
    const float* W1     = (const float*)d_in[11];
    const float* b1     = (const float*)d_in[12];
    const float* W4     = (const float*)d_in[13];
    const float* b4     = (const float*)d_in[14];
    float* out = (float*)d_out;

    int N = in_sizes[0] / 6;
    int E = in_sizes[2];

    prep_kernel<<<2048, 256>>>(nf, N, center, W2, b2, W21, b21);
    int nvec = E >> 2;
    edge_kernel<<<(nvec + 255) / 256, 256>>>(ei, ew, E);
    node_kernel<<<1024, 192>>>(Wrel, brel, Wroot, N, center,
                               W1, b1, W4, b4, out);
}

// round 4
// speedup vs baseline: 1.1297x; 1.1297x over previous
#include <cuda_runtime.h>
#include <cstdint>

#define NMAX 200000
#define H_DIM 184
#define L1_DIM 188

// Per-node accumulator: agg (4f) + deg + pad, one 32B sector => the two REDs
// of an edge hit a single L2 line instead of two.
struct __align__(32) NodeAcc {
    float4 agg;
    float  deg;
    float  pad0, pad1, pad2;
};

__device__ NodeAcc      g_nd[NMAX];
__device__ float4       g_x4[NMAX];       // packed node_feat[:, :4]
__device__ unsigned int g_x1[H_DIM];      // column max of h (uint bits; h>=0)
__device__ float        g_x2[H_DIM];      // h[center]

// ---------------------------------------------------------------------------
// Kernel 0: zero scratch + pack node_feat[:, :4] into float4 table
// ---------------------------------------------------------------------------
__global__ void prep_kernel(const float* __restrict__ nf, int n_nodes) {
    int stride = gridDim.x * blockDim.x;
    int tid = blockIdx.x * blockDim.x + threadIdx.x;

    float4* ndf = reinterpret_cast<float4*>(g_nd);       // 2 float4 per node
    int nvec4 = n_nodes * 2;
    for (int i = tid; i < nvec4; i += stride)
        ndf[i] = make_float4(0.f, 0.f, 0.f, 0.f);
    if (tid < H_DIM) g_x1[tid] = 0u;

    for (int i = tid; i < n_nodes; i += stride) {
        const float2* p = reinterpret_cast<const float2*>(nf + (size_t)i * 6);
        float2 a = __ldg(p);
        float2 b = __ldg(p + 1);
        g_x4[i] = make_float4(a.x, a.y, b.x, b.y);
    }
}

// ---------------------------------------------------------------------------
// Kernel 1: edge scatter.  One LDG.128 gather + red.v4 + red.f32, both REDs
// landing in the same 32B sector of g_nd[d].
// ---------------------------------------------------------------------------
__device__ __forceinline__ void do_edge(int s, int d, float w) {
    float4 x = __ldg(&g_x4[s]);
    float* ap = reinterpret_cast<float*>(&g_nd[d]);
    asm volatile("red.global.add.v4.f32 [%0], {%1, %2, %3, %4};"
                 :: "l"(ap), "f"(x.x * w), "f"(x.y * w),
                    "f"(x.z * w), "f"(x.w * w)
                 : "memory");
    asm volatile("red.global.add.f32 [%0], %1;"
                 :: "l"(ap + 4), "f"(1.0f) : "memory");
}

__global__ void __launch_bounds__(256) edge_kernel(const int*   __restrict__ ei,
                                                   const float* __restrict__ ew, int E) {
    int i    = blockIdx.x * blockDim.x + threadIdx.x;
    int nvec = E >> 2;
    if (i < nvec) {
        int4   s = __ldcs(reinterpret_cast<const int4*>(ei) + i);
        int4   d = __ldcs(reinterpret_cast<const int4*>(ei + E) + i);
        float4 w = __ldcs(reinterpret_cast<const float4*>(ew) + i);
        do_edge(s.x, d.x, w.x);
        do_edge(s.y, d.y, w.y);
        do_edge(s.z, d.z, w.z);
        do_edge(s.w, d.w, w.w);
    }
    if (i == 0) {                                // tail (E % 4)
        for (int e = nvec * 4; e < E; e++)
            do_edge(ei[e], ei[E + e], ew[e]);
    }
}

// ---------------------------------------------------------------------------
// Kernel 2: h = relu(mean@W_rel + b_rel + x@W_root), column-parallel;
// per-block running max, one atomicMax per column per block.
// ---------------------------------------------------------------------------
__global__ void __launch_bounds__(192) node_kernel(
        const float* __restrict__ Wrel,
        const float* __restrict__ brel,
        const float* __restrict__ Wroot,
        int N, const int* __restrict__ center) {
    int j = threadIdx.x;
    if (j >= H_DIM) return;

    float wr0 = Wrel[j],             wr1 = Wrel[H_DIM + j];
    float wr2 = Wrel[2 * H_DIM + j], wr3 = Wrel[3 * H_DIM + j];
    float wo0 = Wroot[j],            wo1 = Wroot[H_DIM + j];
    float wo2 = Wroot[2 * H_DIM + j], wo3 = Wroot[3 * H_DIM + j];
    float bj  = brel[j];
    int   c   = *center;

    float m = 0.0f;                              // h >= 0 after ReLU
    for (int node = blockIdx.x; node < N; node += gridDim.x) {
        float4 agg = g_nd[node].agg;             // broadcast within block
        float  deg = g_nd[node].deg;
        float4 x   = g_x4[node];
        float  inv = 1.0f / fmaxf(deg, 1.0f);
        float h = bj;
        h = fmaf(agg.x * inv, wr0, h);
        h = fmaf(agg.y * inv, wr1, h);
        h = fmaf(agg.z * inv, wr2, h);
        h = fmaf(agg.w * inv, wr3, h);
        h = fmaf(x.x, wo0, h);
        h = fmaf(x.y, wo1, h);
        h = fmaf(x.z, wo2, h);
        h = fmaf(x.w, wo3, h);
        h = fmaxf(h, 0.0f);
        m = fmaxf(m, h);
        if (node == c) g_x2[j] = h;
    }
    atomicMax(&g_x1[j], __float_as_uint(m));
}

// ---------------------------------------------------------------------------
// Kernel 3: head MLP, 1024 threads.  W1 L2-prefetch at entry hides DRAM.
// ---------------------------------------------------------------------------
__global__ void __launch_bounds__(1024) head_kernel(
        const float* __restrict__ nf,
        const int*   __restrict__ center,
        const float* __restrict__ W2,  const float* __restrict__ b2,
        const float* __restrict__ W21, const float* __restrict__ b21,
        const float* __restrict__ W1,  const float* __restrict__ b1,
        const float* __restrict__ W4,  const float* __restrict__ b4,
        float* __restrict__ out) {
    __shared__ float md1[16], md2[16];
    __shared__ float gvec[H_DIM + 16];           // [x2-x1 (184), md2 (16)]
    __shared__ float part[5][192];
    __shared__ float g1[192];
    int tid = threadIdx.x;
    int c = *center;

    // prefetch W1 (204*188 floats = 153KB) + W4 into L2, fire-and-forget
    {
        const int W1_LINES = ((H_DIM + 16) * L1_DIM * 4 + 127) / 128;   // 1199
        for (int l = tid; l < W1_LINES; l += 1024) {
            const char* p = reinterpret_cast<const char*>(W1) + (size_t)l * 128;
            asm volatile("prefetch.global.L2 [%0];" :: "l"(p));
        }
        if (tid < 30) {
            const char* p = reinterpret_cast<const char*>(W4) + (size_t)tid * 128;
            asm volatile("prefetch.global.L2 [%0];" :: "l"(p));
        }
    }

    if (tid < 16) {
        float m0 = nf[(size_t)c * 6 + 4];
        float m1 = nf[(size_t)c * 6 + 5];
        md1[tid] = fmaxf(fmaf(m0, W2[tid], fmaf(m1, W2[16 + tid], b2[tid])), 0.0f);
    }
    __syncthreads();
    if (tid < 16) {
        float s = b21[tid];
        #pragma unroll
        for (int k = 0; k < 16; k++) s = fmaf(md1[k], W21[k * 16 + tid], s);
        md2[tid] = fmaxf(s, 0.0f);
    }
    __syncthreads();
    if (tid < H_DIM)
        gvec[tid] = g_x2[tid] - __uint_as_float(g_x1[tid]);
    else if (tid < H_DIM + 16)
        gvec[tid] = md2[tid - H_DIM];
    __syncthreads();

    // 200x188 matvec: slice s of 5 handles k in [s*40, s*40+40)
    {
        int t = tid % 192;
        int s = tid / 192;
        if (s < 5) {
            float acc = 0.0f;
            int k0 = s * 40;
            if (t < L1_DIM) {
                #pragma unroll 8
                for (int k = k0; k < k0 + 40; k++)
                    acc = fmaf(gvec[k], W1[k * L1_DIM + t], acc);
            }
            part[s][t] = acc;
        }
    }
    __syncthreads();
    if (tid < L1_DIM) {
        float s = b1[tid] + part[0][tid] + part[1][tid] + part[2][tid]
                + part[3][tid] + part[4][tid];
        g1[tid] = fmaxf(s, 0.0f);
    }
    __syncthreads();
    // out = g1 @ W4 + b4 : one warp per output, lanes split k
    if (tid < 160) {
        int o    = tid >> 5;
        int lane = tid & 31;
        float s = 0.0f;
        for (int k = lane; k < L1_DIM; k += 32)
            s = fmaf(g1[k], W4[k * 5 + o], s);
        #pragma unroll
        for (int off = 16; off > 0; off >>= 1)
            s += __shfl_down_sync(0xffffffff, s, off);
        if (lane == 0) out[o] = s + b4[o];
    }
}

// ---------------------------------------------------------------------------
extern "C" void kernel_launch(void* const* d_in, const int* in_sizes, int n_in,
                              void* d_out, int out_size) {
    const float* nf     = (const float*)d_in[0];
    const int*   ei     = (const int*)  d_in[1];
    const float* ew     = (const float*)d_in[2];
    const int*   center = (const int*)  d_in[3];
    const float* Wrel   = (const float*)d_in[4];
    const float* brel   = (const float*)d_in[5];
    const float* Wroot  = (const float*)d_in[6];
    const float* W2     = (const float*)d_in[7];
    const float* b2     = (const float*)d_in[8];
    const float* W21    = (const float*)d_in[9];
    const float* b21    = (const float*)d_in[10];
    const float* W1     = (const float*)d_in[11];
    const float* b1     = (const float*)d_in[12];
    const float* W4     = (const float*)d_in[13];
    const float* b4     = (const float*)d_in[14];
    float* out = (float*)d_out;

    int N = in_sizes[0] / 6;
    int E = in_sizes[2];

    prep_kernel<<<2048, 256>>>(nf, N);
    int nvec = E >> 2;
    edge_kernel<<<(nvec + 255) / 256, 256>>>(ei, ew, E);
    node_kernel<<<1024, 192>>>(Wrel, brel, Wroot, N, center);
    head_kernel<<<1, 1024>>>(nf, center, W2, b2, W21, b21, W1, b1, W4, b4, out);
}